// round 14
// baseline (speedup 1.0000x reference)
#include <cuda_runtime.h>
#include <cuda_bf16.h>
#include <cuda_fp16.h>
#include <math.h>

#define Bn   8
#define Hh   128
#define Wd   128
#define Cc   192
#define Gg   6
#define GC   32
#define KK2  9
#define NFUS 162     // 108 offsets + 54 mask logits
#define M_PIX (Bn*Hh*Wd)   // 131072

// Scratch (device globals — no runtime allocation allowed)
__device__ __half g_xproj [(size_t)M_PIX * Cc];      // x_proj as fp16
__device__ __half g_tmp   [(size_t)M_PIX * Cc];      // dw output as fp16
__device__ __half g_offmsk[(size_t)M_PIX * NFUS];    // offsets|mask as fp16
__device__ float g_bfuse [NFUS];
__device__ unsigned g_wfrag_in [12 * 24 * 64];       // w_in  fragment-major fp16
__device__ unsigned g_wfrag_out[12 * 24 * 64];       // w_out fragment-major fp16
__device__ unsigned g_wffrag   [12 * 24 * 64];       // fused W fragment-major fp16, N padded->192

// ---------------------------------------------------------------------------
// helpers
// ---------------------------------------------------------------------------
__device__ __forceinline__ unsigned f16pair(float a, float b) {
    __half2 t = __floats2half2_rn(a, b);   // a -> low half (even k)
    return *reinterpret_cast<unsigned*>(&t);
}
__device__ __forceinline__ void mma_f16(float* d, const unsigned* a, unsigned b0, unsigned b1) {
    asm volatile(
        "mma.sync.aligned.m16n8k16.row.col.f32.f16.f16.f32 "
        "{%0,%1,%2,%3}, {%4,%5,%6,%7}, {%8,%9}, {%0,%1,%2,%3};\n"
        : "+f"(d[0]), "+f"(d[1]), "+f"(d[2]), "+f"(d[3])
        : "r"(a[0]), "r"(a[1]), "r"(a[2]), "r"(a[3]), "r"(b0), "r"(b1));
}

// ---------------------------------------------------------------------------
// ONE prep kernel: packs w_in / w_out fragments, computes+packs the fused
// offset/mask weight W_f = w_pw @ [w_off|w_mask] per fragment element
// (N padded to 192, zeros beyond 162), and the fused bias.
// Layouts: wfrag[(kt*24 + n8)*64 + lane*2 + which] fp16.
// ---------------------------------------------------------------------------
__device__ __forceinline__ void pack192h(const float* __restrict__ w,
                                         unsigned* __restrict__ wfrag, int i)
{
    int kt = i / (24 * 32);
    int r = i % (24 * 32);
    int n8 = r / 32;
    int lane = r % 32;
    int gid = lane >> 2, tig = lane & 3;
    int n = n8 * 8 + gid;
#pragma unroll
    for (int which = 0; which < 2; which++) {
        int k0 = kt * 16 + which * 8 + tig * 2;
        float v0 = w[(size_t)k0 * Cc + n];
        float v1 = w[(size_t)(k0 + 1) * Cc + n];
        wfrag[(kt * 24 + n8) * 64 + lane * 2 + which] = f16pair(v0, v1);
    }
}

__device__ __forceinline__ void packwf_direct(
    const float* __restrict__ wpw, const float* __restrict__ woff,
    const float* __restrict__ wmask, unsigned* __restrict__ wffrag, int i)
{
    int kt = i / (24 * 32);
    int r = i % (24 * 32);
    int n8 = r / 32;
    int lane = r % 32;
    int gid = lane >> 2, tig = lane & 3;
    int n = n8 * 8 + gid;
#pragma unroll
    for (int which = 0; which < 2; which++) {
        int k0 = kt * 16 + which * 8 + tig * 2;
        float v0 = 0.f, v1 = 0.f;
        if (n < NFUS) {
            const float* w0 = wpw + (size_t)k0 * Cc;
            const float* w1 = w0 + Cc;
            if (n < 108) {
                for (int o = 0; o < Cc; o++) {
                    float wc = woff[(size_t)o * 108 + n];
                    v0 = fmaf(w0[o], wc, v0);
                    v1 = fmaf(w1[o], wc, v1);
                }
            } else {
                int n2 = n - 108;
                for (int o = 0; o < Cc; o++) {
                    float wc = wmask[(size_t)o * 54 + n2];
                    v0 = fmaf(w0[o], wc, v0);
                    v1 = fmaf(w1[o], wc, v1);
                }
            }
        }
        wffrag[(kt * 24 + n8) * 64 + lane * 2 + which] = f16pair(v0, v1);
    }
}

__global__ void prep_all(const float* __restrict__ w_in, const float* __restrict__ w_out,
                         const float* __restrict__ wpw, const float* __restrict__ bpw,
                         const float* __restrict__ woff, const float* __restrict__ boff,
                         const float* __restrict__ wmask, const float* __restrict__ bmask,
                         unsigned* __restrict__ fin, unsigned* __restrict__ fout,
                         unsigned* __restrict__ ffw, float* __restrict__ bf)
{
    int i = blockIdx.x * blockDim.x + threadIdx.x;
    if (i < 9216)              pack192h(w_in,  fin,  i);
    else if (i < 18432)        pack192h(w_out, fout, i - 9216);
    else if (i < 27648)        packwf_direct(wpw, woff, wmask, ffw, i - 18432);
    else if (i < 27648 + NFUS) {
        int n = i - 27648;
        float acc = (n < 108) ? boff[n] : bmask[n - 108];
        if (n < 108) {
            for (int o = 0; o < Cc; o++) acc = fmaf(bpw[o], woff[(size_t)o * 108 + n], acc);
        } else {
            int n2 = n - 108;
            for (int o = 0; o < Cc; o++) acc = fmaf(bpw[o], wmask[(size_t)o * 54 + n2], acc);
        }
        bf[n] = acc;
    }
}

// ---------------------------------------------------------------------------
// Smem-free fp16 GEMM, full N=192 per block, fp16 output (x_proj).
// Grid M/128, 8 warps: 4 along M x 2 along N, warp tile 32x96.
// ---------------------------------------------------------------------------
__global__ __launch_bounds__(256) void gemm_f16(
    const float* __restrict__ A, const unsigned* __restrict__ wfrag,
    const float* __restrict__ bias, __half* __restrict__ C)
{
    const int tid = threadIdx.x;
    const int wid = tid >> 5;
    const int lane = tid & 31;
    const int gid = lane >> 2;
    const int tig = lane & 3;
    const int bm = blockIdx.x * 128 + (wid & 3) * 32;
    const int n8base = (wid >> 2) * 12;
    const uint2* wf2 = reinterpret_cast<const uint2*>(wfrag);

    float acc[2][12][4];
#pragma unroll
    for (int mt = 0; mt < 2; mt++)
#pragma unroll
        for (int nt = 0; nt < 12; nt++)
#pragma unroll
            for (int r = 0; r < 4; r++) acc[mt][nt][r] = 0.f;

    const float* ap0[2];
    const float* ap1[2];
#pragma unroll
    for (int mt = 0; mt < 2; mt++) {
        ap0[mt] = A + (size_t)(bm + mt * 16 + gid) * Cc + tig * 2;
        ap1[mt] = A + (size_t)(bm + mt * 16 + gid + 8) * Cc + tig * 2;
    }

    float2 av[2][4];
    auto loadA = [&](int kt) {
#pragma unroll
        for (int mt = 0; mt < 2; mt++) {
            av[mt][0] = *reinterpret_cast<const float2*>(ap0[mt] + kt * 16);
            av[mt][1] = *reinterpret_cast<const float2*>(ap1[mt] + kt * 16);
            av[mt][2] = *reinterpret_cast<const float2*>(ap0[mt] + kt * 16 + 8);
            av[mt][3] = *reinterpret_cast<const float2*>(ap1[mt] + kt * 16 + 8);
        }
    };

    loadA(0);
#pragma unroll
    for (int kt = 0; kt < 12; kt++) {
        unsigned ah[2][4];
#pragma unroll
        for (int mt = 0; mt < 2; mt++)
#pragma unroll
            for (int r = 0; r < 4; r++)
                ah[mt][r] = f16pair(av[mt][r].x, av[mt][r].y);
        if (kt < 11) loadA(kt + 1);

#pragma unroll
        for (int nt = 0; nt < 12; nt++) {
            uint2 bh = wf2[(size_t)(kt * 24 + n8base + nt) * 32 + lane];
#pragma unroll
            for (int mt = 0; mt < 2; mt++)
                mma_f16(acc[mt][nt], ah[mt], bh.x, bh.y);
        }
    }

#pragma unroll
    for (int mt = 0; mt < 2; mt++) {
        int row0 = bm + mt * 16 + gid;
#pragma unroll
        for (int nt = 0; nt < 12; nt++) {
            int col = (n8base + nt) * 8 + tig * 2;
            float2 bv = *reinterpret_cast<const float2*>(&bias[col]);
            __half2 h0 = __floats2half2_rn(acc[mt][nt][0] + bv.x, acc[mt][nt][1] + bv.y);
            __half2 h1 = __floats2half2_rn(acc[mt][nt][2] + bv.x, acc[mt][nt][3] + bv.y);
            *reinterpret_cast<__half2*>(&C[(size_t)row0 * Cc + col]) = h0;
            *reinterpret_cast<__half2*>(&C[(size_t)(row0 + 8) * Cc + col]) = h1;
        }
    }
}

// ---------------------------------------------------------------------------
// Smem-free fp16 GEMM: offmsk[M,162] = A(fp16)[M,192] @ WFfrag + bias.
// Same full-N structure as gemm_f16 (N padded to 192; stores guarded).
// ---------------------------------------------------------------------------
__global__ __launch_bounds__(256) void gemm_plain_direct(
    const __half* __restrict__ A, const unsigned* __restrict__ wffrag,
    const float* __restrict__ bias, __half* __restrict__ C)
{
    const int tid = threadIdx.x;
    const int wid = tid >> 5;
    const int lane = tid & 31;
    const int gid = lane >> 2;
    const int tig = lane & 3;
    const int bm = blockIdx.x * 128 + (wid & 3) * 32;
    const int n8base = (wid >> 2) * 12;
    const uint2* wf2 = reinterpret_cast<const uint2*>(wffrag);

    float acc[2][12][4];
#pragma unroll
    for (int mt = 0; mt < 2; mt++)
#pragma unroll
        for (int nt = 0; nt < 12; nt++)
#pragma unroll
            for (int r = 0; r < 4; r++) acc[mt][nt][r] = 0.f;

    const __half* ap0[2];
    const __half* ap1[2];
#pragma unroll
    for (int mt = 0; mt < 2; mt++) {
        ap0[mt] = A + (size_t)(bm + mt * 16 + gid) * Cc + tig * 2;
        ap1[mt] = A + (size_t)(bm + mt * 16 + gid + 8) * Cc + tig * 2;
    }

    unsigned ar[2][4];
    auto loadA = [&](int kt) {
#pragma unroll
        for (int mt = 0; mt < 2; mt++) {
            ar[mt][0] = *reinterpret_cast<const unsigned*>(ap0[mt] + kt * 16);
            ar[mt][1] = *reinterpret_cast<const unsigned*>(ap1[mt] + kt * 16);
            ar[mt][2] = *reinterpret_cast<const unsigned*>(ap0[mt] + kt * 16 + 8);
            ar[mt][3] = *reinterpret_cast<const unsigned*>(ap1[mt] + kt * 16 + 8);
        }
    };

    loadA(0);
#pragma unroll
    for (int kt = 0; kt < 12; kt++) {
        unsigned a0[2][4];
#pragma unroll
        for (int mt = 0; mt < 2; mt++)
#pragma unroll
            for (int r = 0; r < 4; r++) a0[mt][r] = ar[mt][r];
        if (kt < 11) loadA(kt + 1);

#pragma unroll
        for (int nt = 0; nt < 12; nt++) {
            uint2 bh = wf2[(size_t)(kt * 24 + n8base + nt) * 32 + lane];
#pragma unroll
            for (int mt = 0; mt < 2; mt++)
                mma_f16(acc[mt][nt], a0[mt], bh.x, bh.y);
        }
    }

#pragma unroll
    for (int mt = 0; mt < 2; mt++) {
        int row0 = bm + mt * 16 + gid;
#pragma unroll
        for (int nt = 0; nt < 12; nt++) {
            int col = (n8base + nt) * 8 + tig * 2;
            if (col + 1 < NFUS) {
                float b0 = bias[col];
                float b1 = bias[col + 1];
                __half2 h0 = __floats2half2_rn(acc[mt][nt][0] + b0, acc[mt][nt][1] + b1);
                __half2 h1 = __floats2half2_rn(acc[mt][nt][2] + b0, acc[mt][nt][3] + b1);
                *reinterpret_cast<__half2*>(&C[(size_t)row0 * NFUS + col]) = h0;
                *reinterpret_cast<__half2*>(&C[(size_t)(row0 + 8) * NFUS + col]) = h1;
            }
        }
    }
}

// ---------------------------------------------------------------------------
// Depthwise 3x3 + bias + SiLU, register-blocked, fp16 output.
// ---------------------------------------------------------------------------
__global__ __launch_bounds__(256) void dw_silu(
    const float4* __restrict__ x, const float4* __restrict__ wdw,
    const float4* __restrict__ bdw, __half* __restrict__ out)
{
    const int C4 = Cc / 4;        // 48
    const int RW = Wd / 4;
    const size_t total = (size_t)(M_PIX / 4) * C4;
    size_t idx = (size_t)blockIdx.x * blockDim.x + threadIdx.x;
    if (idx >= total) return;

    int c4 = (int)(idx % C4);
    int run = (int)(idx / C4);
    int w0 = (run % RW) * 4;
    int h = (run / RW) % Hh;
    int b = run / (RW * Hh);

    float4 bias = bdw[c4];
    float4 acc[4] = {bias, bias, bias, bias};
    const float4 z = make_float4(0.f, 0.f, 0.f, 0.f);

#pragma unroll
    for (int ky = 0; ky < 3; ky++) {
        int hy = h + ky - 1;
        if (hy < 0 || hy >= Hh) continue;
        const float4* row = x + ((size_t)(b * Hh + hy) * Wd) * C4 + c4;
        float4 xv[6];
        xv[0] = (w0 > 0) ? row[(size_t)(w0 - 1) * C4] : z;
#pragma unroll
        for (int t = 0; t < 4; t++) xv[1 + t] = row[(size_t)(w0 + t) * C4];
        xv[5] = (w0 + 4 < Wd) ? row[(size_t)(w0 + 4) * C4] : z;

        float4 wt[3];
#pragma unroll
        for (int kx = 0; kx < 3; kx++) wt[kx] = wdw[(ky * 3 + kx) * C4 + c4];

#pragma unroll
        for (int ow = 0; ow < 4; ow++) {
#pragma unroll
            for (int kx = 0; kx < 3; kx++) {
                float4 v = xv[ow + kx];
                acc[ow].x = fmaf(v.x, wt[kx].x, acc[ow].x);
                acc[ow].y = fmaf(v.y, wt[kx].y, acc[ow].y);
                acc[ow].z = fmaf(v.z, wt[kx].z, acc[ow].z);
                acc[ow].w = fmaf(v.w, wt[kx].w, acc[ow].w);
            }
        }
    }

#pragma unroll
    for (int ow = 0; ow < 4; ow++) {
        float4 a = acc[ow];
        a.x = a.x / (1.f + __expf(-a.x));
        a.y = a.y / (1.f + __expf(-a.y));
        a.z = a.z / (1.f + __expf(-a.z));
        a.w = a.w / (1.f + __expf(-a.w));
        uint2 pk;
        pk.x = f16pair(a.x, a.y);
        pk.y = f16pair(a.z, a.w);
        *reinterpret_cast<uint2*>(
            &out[((size_t)(b * Hh + h) * Wd + (w0 + ow)) * Cc + c4 * 4]) = pk;
    }
}

// ---------------------------------------------------------------------------
// FUSED: softmax + deformable bilinear sampling (half2 lerp) + final GEMM.
// Tap meta packed in one float4: {fw-half2, fh-half2, a, base}.
// smem: xs 10816 + tapm 9216 + As 24576 = 44608 B (4 blocks/SM).
// ---------------------------------------------------------------------------
#define SM_XS    0
#define SM_TM    10816
#define SM_AS    20032
#define SM_TOTAL 44608

__global__ __launch_bounds__(256) void deform_gemm(
    const __half* __restrict__ xproj, const __half* __restrict__ offmsk,
    const unsigned* __restrict__ wfrag, const float* __restrict__ bias,
    float* __restrict__ out)
{
    extern __shared__ char smem_raw[];
    __half2* xs = reinterpret_cast<__half2*>(smem_raw + SM_XS);        // [169][16]
    float4* tapm = reinterpret_cast<float4*>(smem_raw + SM_TM);        // [64][9]
    unsigned* As = reinterpret_cast<unsigned*>(smem_raw + SM_AS);      // [12][4][128] fp16

    const int tile = blockIdx.x;
    const int tid = threadIdx.x;
    const int wid = tid >> 5;
    const int lane = tid & 31;

    const int b  = tile >> 8;
    const int ty = (tile >> 4) & 15;
    const int tx = tile & 15;
    const int h0 = ty * 8, w0 = tx * 8;

    const int half = lane >> 4;
    const int ch = lane & 15;

    for (int g = 0; g < Gg; g++) {
        if (g) __syncthreads();

        if (tid < 64) {
            int py = tid >> 3, px = tid & 7;
            int h = h0 + py, w = w0 + px;
            const __half* om = offmsk + (((size_t)(b * Hh + h)) * Wd + w) * NFUS;
            float m[KK2], mx = -1e30f;
#pragma unroll
            for (int k = 0; k < KK2; k++) {
                m[k] = __half2float(om[108 + g * KK2 + k]);
                mx = fmaxf(mx, m[k]);
            }
            float sum = 0.f;
#pragma unroll
            for (int k = 0; k < KK2; k++) { m[k] = __expf(m[k] - mx); sum += m[k]; }
            float inv = 1.f / sum;
#pragma unroll
            for (int k = 0; k < KK2; k++) {
                float a = m[k] * inv;
                float ph = (float)h + (float)(k / 3 - 1)
                         + __half2float(om[g * 18 + 2 * k])     * 0.1f;
                float pw = (float)w + (float)(k % 3 - 1)
                         + __half2float(om[g * 18 + 2 * k + 1]) * 0.1f;
                ph = fminf(fmaxf(ph, 0.f), (float)(Hh - 1));
                pw = fminf(fmaxf(pw, 0.f), (float)(Wd - 1));
                int hf = (int)ph;
                int wf = (int)pw;
                float fh = ph - (float)hf;
                float fw = pw - (float)wf;
                int hl = min(max(hf - (h0 - 2), 0), 11);
                int wl = min(max(wf - (w0 - 2), 0), 11);
                __half2 fw2 = __floats2half2_rn(fw, fw);
                __half2 fh2 = __floats2half2_rn(fh, fh);
                float4 tm;
                tm.x = __uint_as_float(*reinterpret_cast<unsigned*>(&fw2));
                tm.y = __uint_as_float(*reinterpret_cast<unsigned*>(&fh2));
                tm.z = a;
                tm.w = __int_as_float((hl * 13 + wl) * 16);
                tapm[tid * KK2 + k] = tm;
            }
        } else {
            for (int idx = tid - 64; idx < 13 * 13 * 8; idx += 192) {
                int cell = idx >> 3;
                int c4 = idx & 7;
                int hi = cell / 13, wi = cell % 13;
                int row = min(max(h0 - 2 + hi, 0), Hh - 1);
                int col = min(max(w0 - 2 + wi, 0), Wd - 1);
                uint2 v = *reinterpret_cast<const uint2*>(
                    &xproj[(((size_t)(b * Hh + row)) * Wd + col) * Cc + g * GC + c4 * 4]);
                xs[cell * 16 + c4 * 2]     = *reinterpret_cast<__half2*>(&v.x);
                xs[cell * 16 + c4 * 2 + 1] = *reinterpret_cast<__half2*>(&v.y);
            }
        }
        __syncthreads();

        const int ktile = g * 2 + (ch >> 3);
        const int tigw = ch & 3;
        const int khalf = (ch >> 2) & 1;
#pragma unroll
        for (int pass = 0; pass < 4; pass++) {
            int p = wid * 8 + pass * 2 + half;
            float2 acc = make_float2(0.f, 0.f);
#pragma unroll
            for (int k = 0; k < KK2; k++) {
                float4 tm = tapm[p * KK2 + k];
                unsigned fw2u = __float_as_uint(tm.x);
                unsigned fh2u = __float_as_uint(tm.y);
                __half2 fw2 = *reinterpret_cast<__half2*>(&fw2u);
                __half2 fh2 = *reinterpret_cast<__half2*>(&fh2u);
                int c00 = __float_as_int(tm.w) + ch;
                __half2 v00 = xs[c00];
                __half2 v01 = xs[c00 + 16];
                __half2 v10 = xs[c00 + 208];
                __half2 v11 = xs[c00 + 224];
                __half2 t  = __hfma2(fw2, __hsub2(v01, v00), v00);
                __half2 bo = __hfma2(fw2, __hsub2(v11, v10), v10);
                __half2 val = __hfma2(fh2, __hsub2(bo, t), t);
                float2 vf = __half22float2(val);
                acc.x = fmaf(tm.z, vf.x, acc.x);
                acc.y = fmaf(tm.z, vf.y, acc.y);
            }
            int mb = p >> 4;
            int gp = p & 7;
            int half_r = (p >> 3) & 1;
            int reg = half_r + 2 * khalf;
            As[(ktile * 4 + mb) * 128 + (gp * 4 + tigw) * 4 + reg] = f16pair(acc.x, acc.y);
        }
    }
    __syncthreads();

    // GEMM phase: [64,192] @ [192,192] fp16
    const uint2* wf2 = reinterpret_cast<const uint2*>(wfrag);
    float acc[4][3][4];
#pragma unroll
    for (int mt = 0; mt < 4; mt++)
#pragma unroll
        for (int nt = 0; nt < 3; nt++)
#pragma unroll
            for (int r = 0; r < 4; r++) acc[mt][nt][r] = 0.f;

    uint2 bh[2][3];
    auto loadB = [&](int kt, int pb) {
#pragma unroll
        for (int nt = 0; nt < 3; nt++)
            bh[pb][nt] = wf2[(kt * 24 + wid * 3 + nt) * 32 + lane];
    };
    loadB(0, 0);
    int pb = 0;
#pragma unroll
    for (int kt = 0; kt < 12; kt++) {
        if (kt < 11) loadB(kt + 1, pb ^ 1);
        unsigned ah[4][4];
#pragma unroll
        for (int mb = 0; mb < 4; mb++) {
            uint4 u = *reinterpret_cast<const uint4*>(&As[(kt * 4 + mb) * 128 + lane * 4]);
            ah[mb][0] = u.x; ah[mb][1] = u.y; ah[mb][2] = u.z; ah[mb][3] = u.w;
        }
#pragma unroll
        for (int mt = 0; mt < 4; mt++)
#pragma unroll
            for (int nt = 0; nt < 3; nt++)
                mma_f16(acc[mt][nt], ah[mt], bh[pb][nt].x, bh[pb][nt].y);
        pb ^= 1;
    }

    const int gid = lane >> 2;
    const int tig = lane & 3;
#pragma unroll
    for (int mt = 0; mt < 4; mt++) {
#pragma unroll
        for (int rr = 0; rr < 2; rr++) {
            int p = mt * 16 + rr * 8 + gid;
            size_t pix = ((size_t)(b * Hh + h0 + (p >> 3)) * Wd + w0 + (p & 7));
#pragma unroll
            for (int nt = 0; nt < 3; nt++) {
                int n = (wid * 3 + nt) * 8 + tig * 2;
                float2 v;
                v.x = acc[mt][nt][rr * 2 + 0] + bias[n];
                v.y = acc[mt][nt][rr * 2 + 1] + bias[n + 1];
                *reinterpret_cast<float2*>(&out[pix * Cc + n]) = v;
            }
        }
    }
}

// ---------------------------------------------------------------------------
// Launch
// ---------------------------------------------------------------------------
extern "C" void kernel_launch(void* const* d_in, const int* in_sizes, int n_in,
                              void* d_out, int out_size)
{
    const float* x      = (const float*)d_in[0];
    const float* w_in   = (const float*)d_in[1];
    const float* b_in   = (const float*)d_in[2];
    const float* w_dw   = (const float*)d_in[3];
    const float* b_dw   = (const float*)d_in[4];
    const float* w_pw   = (const float*)d_in[5];
    const float* b_pw   = (const float*)d_in[6];
    const float* w_off  = (const float*)d_in[7];
    const float* b_off  = (const float*)d_in[8];
    const float* w_mask = (const float*)d_in[9];
    const float* b_mask = (const float*)d_in[10];
    const float* w_out  = (const float*)d_in[11];
    const float* b_out  = (const float*)d_in[12];
    float* out = (float*)d_out;

    __half *xproj, *offmsk, *tmp;
    float *bfu;
    unsigned *wfin, *wfout, *wff;
    cudaGetSymbolAddress((void**)&xproj,  g_xproj);
    cudaGetSymbolAddress((void**)&tmp,    g_tmp);
    cudaGetSymbolAddress((void**)&offmsk, g_offmsk);
    cudaGetSymbolAddress((void**)&bfu,    g_bfuse);
    cudaGetSymbolAddress((void**)&wfin,   g_wfrag_in);
    cudaGetSymbolAddress((void**)&wfout,  g_wfrag_out);
    cudaGetSymbolAddress((void**)&wff,    g_wffrag);

    cudaFuncSetAttribute(deform_gemm, cudaFuncAttributeMaxDynamicSharedMemorySize, SM_TOTAL);

    // 0. single prep kernel: pack w_in/w_out, fuse+pack W_f (N pad 192), bias
    prep_all<<<(27648 + NFUS + 255) / 256, 256>>>(
        w_in, w_out, w_pw, b_pw, w_off, b_off, w_mask, b_mask,
        wfin, wfout, wff, bfu);
    // 1. x_proj = x @ w_in + b_in  (fp16 mma, smem-free, fp16 out)
    gemm_f16<<<M_PIX / 128, 256>>>(x, wfin, b_in, xproj);
    // 2. depthwise 3x3 + SiLU -> fp16 tmp
    {
        size_t n = (size_t)(M_PIX / 4) * (Cc / 4);
        dw_silu<<<(unsigned)((n + 255) / 256), 256>>>(
            (const float4*)x, (const float4*)w_dw, (const float4*)b_dw, tmp);
    }
    // 3. [offsets|mask] = dwout_fp16 @ W_f(fp16, full-N) + b_f -> fp16 offmsk
    gemm_plain_direct<<<M_PIX / 128, 256>>>(tmp, wff, bfu, offmsk);
    // 4+5. fused softmax + deformable sampling (half2 lerp) + final GEMM -> out
    deform_gemm<<<2048, 256, SM_TOTAL>>>(xproj, offmsk, wfout, b_out, out);
}

// round 15
// speedup vs baseline: 1.0569x; 1.0569x over previous
#include <cuda_runtime.h>
#include <cuda_bf16.h>
#include <cuda_fp16.h>
#include <math.h>

#define Bn   8
#define Hh   128
#define Wd   128
#define Cc   192
#define Gg   6
#define GC   32
#define KK2  9
#define NFUS 162     // 108 offsets + 54 mask logits
#define M_PIX (Bn*Hh*Wd)   // 131072

// Scratch (device globals — no runtime allocation allowed)
__device__ __half g_xproj [(size_t)M_PIX * Cc];      // x_proj as fp16
__device__ __half g_tmp   [(size_t)M_PIX * Cc];      // dw output as fp16
__device__ __half g_offmsk[(size_t)M_PIX * NFUS];    // offsets|mask as fp16
__device__ float g_bfuse [NFUS];
__device__ unsigned g_wfrag_in [12 * 24 * 64];       // w_in  fragment-major fp16
__device__ unsigned g_wfrag_out[12 * 24 * 64];       // w_out fragment-major fp16
__device__ unsigned g_wffrag   [12 * 24 * 64];       // fused W fragment-major fp16, N padded->192

// ---------------------------------------------------------------------------
// helpers
// ---------------------------------------------------------------------------
__device__ __forceinline__ unsigned f16pair(float a, float b) {
    __half2 t = __floats2half2_rn(a, b);   // a -> low half (even k)
    return *reinterpret_cast<unsigned*>(&t);
}
__device__ __forceinline__ void mma_f16(float* d, const unsigned* a, unsigned b0, unsigned b1) {
    asm volatile(
        "mma.sync.aligned.m16n8k16.row.col.f32.f16.f16.f32 "
        "{%0,%1,%2,%3}, {%4,%5,%6,%7}, {%8,%9}, {%0,%1,%2,%3};\n"
        : "+f"(d[0]), "+f"(d[1]), "+f"(d[2]), "+f"(d[3])
        : "r"(a[0]), "r"(a[1]), "r"(a[2]), "r"(a[3]), "r"(b0), "r"(b1));
}

// ---------------------------------------------------------------------------
// ONE prep kernel: packs w_in / w_out fragments, computes+packs the fused
// offset/mask weight W_f = w_pw @ [w_off|w_mask] per fragment element
// (N padded to 192, zeros beyond 162), and the fused bias.
// Layouts: wfrag[(kt*24 + n8)*64 + lane*2 + which] fp16.
// ---------------------------------------------------------------------------
__device__ __forceinline__ void pack192h(const float* __restrict__ w,
                                         unsigned* __restrict__ wfrag, int i)
{
    int kt = i / (24 * 32);
    int r = i % (24 * 32);
    int n8 = r / 32;
    int lane = r % 32;
    int gid = lane >> 2, tig = lane & 3;
    int n = n8 * 8 + gid;
#pragma unroll
    for (int which = 0; which < 2; which++) {
        int k0 = kt * 16 + which * 8 + tig * 2;
        float v0 = w[(size_t)k0 * Cc + n];
        float v1 = w[(size_t)(k0 + 1) * Cc + n];
        wfrag[(kt * 24 + n8) * 64 + lane * 2 + which] = f16pair(v0, v1);
    }
}

__device__ __forceinline__ void packwf_direct(
    const float* __restrict__ wpw, const float* __restrict__ woff,
    const float* __restrict__ wmask, unsigned* __restrict__ wffrag, int i)
{
    int kt = i / (24 * 32);
    int r = i % (24 * 32);
    int n8 = r / 32;
    int lane = r % 32;
    int gid = lane >> 2, tig = lane & 3;
    int n = n8 * 8 + gid;
#pragma unroll
    for (int which = 0; which < 2; which++) {
        int k0 = kt * 16 + which * 8 + tig * 2;
        float v0 = 0.f, v1 = 0.f;
        if (n < NFUS) {
            const float* w0 = wpw + (size_t)k0 * Cc;
            const float* w1 = w0 + Cc;
            if (n < 108) {
                for (int o = 0; o < Cc; o++) {
                    float wc = woff[(size_t)o * 108 + n];
                    v0 = fmaf(w0[o], wc, v0);
                    v1 = fmaf(w1[o], wc, v1);
                }
            } else {
                int n2 = n - 108;
                for (int o = 0; o < Cc; o++) {
                    float wc = wmask[(size_t)o * 54 + n2];
                    v0 = fmaf(w0[o], wc, v0);
                    v1 = fmaf(w1[o], wc, v1);
                }
            }
        }
        wffrag[(kt * 24 + n8) * 64 + lane * 2 + which] = f16pair(v0, v1);
    }
}

__global__ void prep_all(const float* __restrict__ w_in, const float* __restrict__ w_out,
                         const float* __restrict__ wpw, const float* __restrict__ bpw,
                         const float* __restrict__ woff, const float* __restrict__ boff,
                         const float* __restrict__ wmask, const float* __restrict__ bmask,
                         unsigned* __restrict__ fin, unsigned* __restrict__ fout,
                         unsigned* __restrict__ ffw, float* __restrict__ bf)
{
    int i = blockIdx.x * blockDim.x + threadIdx.x;
    if (i < 9216)              pack192h(w_in,  fin,  i);
    else if (i < 18432)        pack192h(w_out, fout, i - 9216);
    else if (i < 27648)        packwf_direct(wpw, woff, wmask, ffw, i - 18432);
    else if (i < 27648 + NFUS) {
        int n = i - 27648;
        float acc = (n < 108) ? boff[n] : bmask[n - 108];
        if (n < 108) {
            for (int o = 0; o < Cc; o++) acc = fmaf(bpw[o], woff[(size_t)o * 108 + n], acc);
        } else {
            int n2 = n - 108;
            for (int o = 0; o < Cc; o++) acc = fmaf(bpw[o], wmask[(size_t)o * 54 + n2], acc);
        }
        bf[n] = acc;
    }
}

// ---------------------------------------------------------------------------
// Smem-free fp16 GEMM (x_proj): warp tile 32x48, grid (2, M/128).
// Block covers 128 rows x 96 cols; 8 warps = 4 along M x 2 along N.
// Small acc tile (48 regs) -> ~3 blocks/SM for latency hiding.
// ---------------------------------------------------------------------------
__global__ __launch_bounds__(256) void gemm_f16(
    const float* __restrict__ A, const unsigned* __restrict__ wfrag,
    const float* __restrict__ bias, __half* __restrict__ C)
{
    const int tid = threadIdx.x;
    const int wid = tid >> 5;
    const int lane = tid & 31;
    const int gid = lane >> 2;
    const int tig = lane & 3;
    const int bm = blockIdx.y * 128 + (wid & 3) * 32;
    const int n8base = blockIdx.x * 12 + (wid >> 2) * 6;
    const uint2* wf2 = reinterpret_cast<const uint2*>(wfrag);

    float acc[2][6][4];
#pragma unroll
    for (int mt = 0; mt < 2; mt++)
#pragma unroll
        for (int nt = 0; nt < 6; nt++)
#pragma unroll
            for (int r = 0; r < 4; r++) acc[mt][nt][r] = 0.f;

    const float* ap0[2];
    const float* ap1[2];
#pragma unroll
    for (int mt = 0; mt < 2; mt++) {
        ap0[mt] = A + (size_t)(bm + mt * 16 + gid) * Cc + tig * 2;
        ap1[mt] = A + (size_t)(bm + mt * 16 + gid + 8) * Cc + tig * 2;
    }

    float2 av[2][4];
    auto loadA = [&](int kt) {
#pragma unroll
        for (int mt = 0; mt < 2; mt++) {
            av[mt][0] = *reinterpret_cast<const float2*>(ap0[mt] + kt * 16);
            av[mt][1] = *reinterpret_cast<const float2*>(ap1[mt] + kt * 16);
            av[mt][2] = *reinterpret_cast<const float2*>(ap0[mt] + kt * 16 + 8);
            av[mt][3] = *reinterpret_cast<const float2*>(ap1[mt] + kt * 16 + 8);
        }
    };

    loadA(0);
#pragma unroll
    for (int kt = 0; kt < 12; kt++) {
        unsigned ah[2][4];
#pragma unroll
        for (int mt = 0; mt < 2; mt++)
#pragma unroll
            for (int r = 0; r < 4; r++)
                ah[mt][r] = f16pair(av[mt][r].x, av[mt][r].y);
        if (kt < 11) loadA(kt + 1);

#pragma unroll
        for (int nt = 0; nt < 6; nt++) {
            uint2 bh = wf2[(size_t)(kt * 24 + n8base + nt) * 32 + lane];
#pragma unroll
            for (int mt = 0; mt < 2; mt++)
                mma_f16(acc[mt][nt], ah[mt], bh.x, bh.y);
        }
    }

#pragma unroll
    for (int mt = 0; mt < 2; mt++) {
        int row0 = bm + mt * 16 + gid;
#pragma unroll
        for (int nt = 0; nt < 6; nt++) {
            int col = (n8base + nt) * 8 + tig * 2;
            float2 bv = *reinterpret_cast<const float2*>(&bias[col]);
            __half2 h0 = __floats2half2_rn(acc[mt][nt][0] + bv.x, acc[mt][nt][1] + bv.y);
            __half2 h1 = __floats2half2_rn(acc[mt][nt][2] + bv.x, acc[mt][nt][3] + bv.y);
            *reinterpret_cast<__half2*>(&C[(size_t)row0 * Cc + col]) = h0;
            *reinterpret_cast<__half2*>(&C[(size_t)(row0 + 8) * Cc + col]) = h1;
        }
    }
}

// ---------------------------------------------------------------------------
// Smem-free fp16 GEMM (offsets/mask): same 32x48 warp-tile structure,
// fp16 A input, fp16 output guarded at NFUS.
// ---------------------------------------------------------------------------
__global__ __launch_bounds__(256) void gemm_plain_direct(
    const __half* __restrict__ A, const unsigned* __restrict__ wffrag,
    const float* __restrict__ bias, __half* __restrict__ C)
{
    const int tid = threadIdx.x;
    const int wid = tid >> 5;
    const int lane = tid & 31;
    const int gid = lane >> 2;
    const int tig = lane & 3;
    const int bm = blockIdx.y * 128 + (wid & 3) * 32;
    const int n8base = blockIdx.x * 12 + (wid >> 2) * 6;
    const uint2* wf2 = reinterpret_cast<const uint2*>(wffrag);

    float acc[2][6][4];
#pragma unroll
    for (int mt = 0; mt < 2; mt++)
#pragma unroll
        for (int nt = 0; nt < 6; nt++)
#pragma unroll
            for (int r = 0; r < 4; r++) acc[mt][nt][r] = 0.f;

    const __half* ap0[2];
    const __half* ap1[2];
#pragma unroll
    for (int mt = 0; mt < 2; mt++) {
        ap0[mt] = A + (size_t)(bm + mt * 16 + gid) * Cc + tig * 2;
        ap1[mt] = A + (size_t)(bm + mt * 16 + gid + 8) * Cc + tig * 2;
    }

    unsigned ar[2][4];
    auto loadA = [&](int kt) {
#pragma unroll
        for (int mt = 0; mt < 2; mt++) {
            ar[mt][0] = *reinterpret_cast<const unsigned*>(ap0[mt] + kt * 16);
            ar[mt][1] = *reinterpret_cast<const unsigned*>(ap1[mt] + kt * 16);
            ar[mt][2] = *reinterpret_cast<const unsigned*>(ap0[mt] + kt * 16 + 8);
            ar[mt][3] = *reinterpret_cast<const unsigned*>(ap1[mt] + kt * 16 + 8);
        }
    };

    loadA(0);
#pragma unroll
    for (int kt = 0; kt < 12; kt++) {
        unsigned a0[2][4];
#pragma unroll
        for (int mt = 0; mt < 2; mt++)
#pragma unroll
            for (int r = 0; r < 4; r++) a0[mt][r] = ar[mt][r];
        if (kt < 11) loadA(kt + 1);

#pragma unroll
        for (int nt = 0; nt < 6; nt++) {
            uint2 bh = wf2[(size_t)(kt * 24 + n8base + nt) * 32 + lane];
#pragma unroll
            for (int mt = 0; mt < 2; mt++)
                mma_f16(acc[mt][nt], a0[mt], bh.x, bh.y);
        }
    }

#pragma unroll
    for (int mt = 0; mt < 2; mt++) {
        int row0 = bm + mt * 16 + gid;
#pragma unroll
        for (int nt = 0; nt < 6; nt++) {
            int col = (n8base + nt) * 8 + tig * 2;
            if (col + 1 < NFUS) {
                float b0 = bias[col];
                float b1 = bias[col + 1];
                __half2 h0 = __floats2half2_rn(acc[mt][nt][0] + b0, acc[mt][nt][1] + b1);
                __half2 h1 = __floats2half2_rn(acc[mt][nt][2] + b0, acc[mt][nt][3] + b1);
                *reinterpret_cast<__half2*>(&C[(size_t)row0 * NFUS + col]) = h0;
                *reinterpret_cast<__half2*>(&C[(size_t)(row0 + 8) * NFUS + col]) = h1;
            }
        }
    }
}

// ---------------------------------------------------------------------------
// Depthwise 3x3 + bias + SiLU, register-blocked, fp16 output.
// ---------------------------------------------------------------------------
__global__ __launch_bounds__(256) void dw_silu(
    const float4* __restrict__ x, const float4* __restrict__ wdw,
    const float4* __restrict__ bdw, __half* __restrict__ out)
{
    const int C4 = Cc / 4;        // 48
    const int RW = Wd / 4;
    const size_t total = (size_t)(M_PIX / 4) * C4;
    size_t idx = (size_t)blockIdx.x * blockDim.x + threadIdx.x;
    if (idx >= total) return;

    int c4 = (int)(idx % C4);
    int run = (int)(idx / C4);
    int w0 = (run % RW) * 4;
    int h = (run / RW) % Hh;
    int b = run / (RW * Hh);

    float4 bias = bdw[c4];
    float4 acc[4] = {bias, bias, bias, bias};
    const float4 z = make_float4(0.f, 0.f, 0.f, 0.f);

#pragma unroll
    for (int ky = 0; ky < 3; ky++) {
        int hy = h + ky - 1;
        if (hy < 0 || hy >= Hh) continue;
        const float4* row = x + ((size_t)(b * Hh + hy) * Wd) * C4 + c4;
        float4 xv[6];
        xv[0] = (w0 > 0) ? row[(size_t)(w0 - 1) * C4] : z;
#pragma unroll
        for (int t = 0; t < 4; t++) xv[1 + t] = row[(size_t)(w0 + t) * C4];
        xv[5] = (w0 + 4 < Wd) ? row[(size_t)(w0 + 4) * C4] : z;

        float4 wt[3];
#pragma unroll
        for (int kx = 0; kx < 3; kx++) wt[kx] = wdw[(ky * 3 + kx) * C4 + c4];

#pragma unroll
        for (int ow = 0; ow < 4; ow++) {
#pragma unroll
            for (int kx = 0; kx < 3; kx++) {
                float4 v = xv[ow + kx];
                acc[ow].x = fmaf(v.x, wt[kx].x, acc[ow].x);
                acc[ow].y = fmaf(v.y, wt[kx].y, acc[ow].y);
                acc[ow].z = fmaf(v.z, wt[kx].z, acc[ow].z);
                acc[ow].w = fmaf(v.w, wt[kx].w, acc[ow].w);
            }
        }
    }

#pragma unroll
    for (int ow = 0; ow < 4; ow++) {
        float4 a = acc[ow];
        a.x = a.x / (1.f + __expf(-a.x));
        a.y = a.y / (1.f + __expf(-a.y));
        a.z = a.z / (1.f + __expf(-a.z));
        a.w = a.w / (1.f + __expf(-a.w));
        uint2 pk;
        pk.x = f16pair(a.x, a.y);
        pk.y = f16pair(a.z, a.w);
        *reinterpret_cast<uint2*>(
            &out[((size_t)(b * Hh + h) * Wd + (w0 + ow)) * Cc + c4 * 4]) = pk;
    }
}

// ---------------------------------------------------------------------------
// FUSED: softmax + deformable bilinear sampling (half2 lerp) + final GEMM.
// Tap meta packed in one float4: {fw-half2, fh-half2, a, base}.
// smem: xs 10816 + tapm 9216 + As 24576 = 44608 B (4 blocks/SM).
// ---------------------------------------------------------------------------
#define SM_XS    0
#define SM_TM    10816
#define SM_AS    20032
#define SM_TOTAL 44608

__global__ __launch_bounds__(256) void deform_gemm(
    const __half* __restrict__ xproj, const __half* __restrict__ offmsk,
    const unsigned* __restrict__ wfrag, const float* __restrict__ bias,
    float* __restrict__ out)
{
    extern __shared__ char smem_raw[];
    __half2* xs = reinterpret_cast<__half2*>(smem_raw + SM_XS);        // [169][16]
    float4* tapm = reinterpret_cast<float4*>(smem_raw + SM_TM);        // [64][9]
    unsigned* As = reinterpret_cast<unsigned*>(smem_raw + SM_AS);      // [12][4][128] fp16

    const int tile = blockIdx.x;
    const int tid = threadIdx.x;
    const int wid = tid >> 5;
    const int lane = tid & 31;

    const int b  = tile >> 8;
    const int ty = (tile >> 4) & 15;
    const int tx = tile & 15;
    const int h0 = ty * 8, w0 = tx * 8;

    const int half = lane >> 4;
    const int ch = lane & 15;

    for (int g = 0; g < Gg; g++) {
        if (g) __syncthreads();

        if (tid < 64) {
            int py = tid >> 3, px = tid & 7;
            int h = h0 + py, w = w0 + px;
            const __half* om = offmsk + (((size_t)(b * Hh + h)) * Wd + w) * NFUS;
            float m[KK2], mx = -1e30f;
#pragma unroll
            for (int k = 0; k < KK2; k++) {
                m[k] = __half2float(om[108 + g * KK2 + k]);
                mx = fmaxf(mx, m[k]);
            }
            float sum = 0.f;
#pragma unroll
            for (int k = 0; k < KK2; k++) { m[k] = __expf(m[k] - mx); sum += m[k]; }
            float inv = 1.f / sum;
#pragma unroll
            for (int k = 0; k < KK2; k++) {
                float a = m[k] * inv;
                float ph = (float)h + (float)(k / 3 - 1)
                         + __half2float(om[g * 18 + 2 * k])     * 0.1f;
                float pw = (float)w + (float)(k % 3 - 1)
                         + __half2float(om[g * 18 + 2 * k + 1]) * 0.1f;
                ph = fminf(fmaxf(ph, 0.f), (float)(Hh - 1));
                pw = fminf(fmaxf(pw, 0.f), (float)(Wd - 1));
                int hf = (int)ph;
                int wf = (int)pw;
                float fh = ph - (float)hf;
                float fw = pw - (float)wf;
                int hl = min(max(hf - (h0 - 2), 0), 11);
                int wl = min(max(wf - (w0 - 2), 0), 11);
                __half2 fw2 = __floats2half2_rn(fw, fw);
                __half2 fh2 = __floats2half2_rn(fh, fh);
                float4 tm;
                tm.x = __uint_as_float(*reinterpret_cast<unsigned*>(&fw2));
                tm.y = __uint_as_float(*reinterpret_cast<unsigned*>(&fh2));
                tm.z = a;
                tm.w = __int_as_float((hl * 13 + wl) * 16);
                tapm[tid * KK2 + k] = tm;
            }
        } else {
            for (int idx = tid - 64; idx < 13 * 13 * 8; idx += 192) {
                int cell = idx >> 3;
                int c4 = idx & 7;
                int hi = cell / 13, wi = cell % 13;
                int row = min(max(h0 - 2 + hi, 0), Hh - 1);
                int col = min(max(w0 - 2 + wi, 0), Wd - 1);
                uint2 v = *reinterpret_cast<const uint2*>(
                    &xproj[(((size_t)(b * Hh + row)) * Wd + col) * Cc + g * GC + c4 * 4]);
                xs[cell * 16 + c4 * 2]     = *reinterpret_cast<__half2*>(&v.x);
                xs[cell * 16 + c4 * 2 + 1] = *reinterpret_cast<__half2*>(&v.y);
            }
        }
        __syncthreads();

        const int ktile = g * 2 + (ch >> 3);
        const int tigw = ch & 3;
        const int khalf = (ch >> 2) & 1;
#pragma unroll
        for (int pass = 0; pass < 4; pass++) {
            int p = wid * 8 + pass * 2 + half;
            float2 acc = make_float2(0.f, 0.f);
#pragma unroll
            for (int k = 0; k < KK2; k++) {
                float4 tm = tapm[p * KK2 + k];
                unsigned fw2u = __float_as_uint(tm.x);
                unsigned fh2u = __float_as_uint(tm.y);
                __half2 fw2 = *reinterpret_cast<__half2*>(&fw2u);
                __half2 fh2 = *reinterpret_cast<__half2*>(&fh2u);
                int c00 = __float_as_int(tm.w) + ch;
                __half2 v00 = xs[c00];
                __half2 v01 = xs[c00 + 16];
                __half2 v10 = xs[c00 + 208];
                __half2 v11 = xs[c00 + 224];
                __half2 t  = __hfma2(fw2, __hsub2(v01, v00), v00);
                __half2 bo = __hfma2(fw2, __hsub2(v11, v10), v10);
                __half2 val = __hfma2(fh2, __hsub2(bo, t), t);
                float2 vf = __half22float2(val);
                acc.x = fmaf(tm.z, vf.x, acc.x);
                acc.y = fmaf(tm.z, vf.y, acc.y);
            }
            int mb = p >> 4;
            int gp = p & 7;
            int half_r = (p >> 3) & 1;
            int reg = half_r + 2 * khalf;
            As[(ktile * 4 + mb) * 128 + (gp * 4 + tigw) * 4 + reg] = f16pair(acc.x, acc.y);
        }
    }
    __syncthreads();

    // GEMM phase: [64,192] @ [192,192] fp16
    const uint2* wf2 = reinterpret_cast<const uint2*>(wfrag);
    float acc[4][3][4];
#pragma unroll
    for (int mt = 0; mt < 4; mt++)
#pragma unroll
        for (int nt = 0; nt < 3; nt++)
#pragma unroll
            for (int r = 0; r < 4; r++) acc[mt][nt][r] = 0.f;

    uint2 bh[2][3];
    auto loadB = [&](int kt, int pb) {
#pragma unroll
        for (int nt = 0; nt < 3; nt++)
            bh[pb][nt] = wf2[(kt * 24 + wid * 3 + nt) * 32 + lane];
    };
    loadB(0, 0);
    int pb = 0;
#pragma unroll
    for (int kt = 0; kt < 12; kt++) {
        if (kt < 11) loadB(kt + 1, pb ^ 1);
        unsigned ah[4][4];
#pragma unroll
        for (int mb = 0; mb < 4; mb++) {
            uint4 u = *reinterpret_cast<const uint4*>(&As[(kt * 4 + mb) * 128 + lane * 4]);
            ah[mb][0] = u.x; ah[mb][1] = u.y; ah[mb][2] = u.z; ah[mb][3] = u.w;
        }
#pragma unroll
        for (int mt = 0; mt < 4; mt++)
#pragma unroll
            for (int nt = 0; nt < 3; nt++)
                mma_f16(acc[mt][nt], ah[mt], bh[pb][nt].x, bh[pb][nt].y);
        pb ^= 1;
    }

    const int gid = lane >> 2;
    const int tig = lane & 3;
#pragma unroll
    for (int mt = 0; mt < 4; mt++) {
#pragma unroll
        for (int rr = 0; rr < 2; rr++) {
            int p = mt * 16 + rr * 8 + gid;
            size_t pix = ((size_t)(b * Hh + h0 + (p >> 3)) * Wd + w0 + (p & 7));
#pragma unroll
            for (int nt = 0; nt < 3; nt++) {
                int n = (wid * 3 + nt) * 8 + tig * 2;
                float2 v;
                v.x = acc[mt][nt][rr * 2 + 0] + bias[n];
                v.y = acc[mt][nt][rr * 2 + 1] + bias[n + 1];
                *reinterpret_cast<float2*>(&out[pix * Cc + n]) = v;
            }
        }
    }
}

// ---------------------------------------------------------------------------
// Launch
// ---------------------------------------------------------------------------
extern "C" void kernel_launch(void* const* d_in, const int* in_sizes, int n_in,
                              void* d_out, int out_size)
{
    const float* x      = (const float*)d_in[0];
    const float* w_in   = (const float*)d_in[1];
    const float* b_in   = (const float*)d_in[2];
    const float* w_dw   = (const float*)d_in[3];
    const float* b_dw   = (const float*)d_in[4];
    const float* w_pw   = (const float*)d_in[5];
    const float* b_pw   = (const float*)d_in[6];
    const float* w_off  = (const float*)d_in[7];
    const float* b_off  = (const float*)d_in[8];
    const float* w_mask = (const float*)d_in[9];
    const float* b_mask = (const float*)d_in[10];
    const float* w_out  = (const float*)d_in[11];
    const float* b_out  = (const float*)d_in[12];
    float* out = (float*)d_out;

    __half *xproj, *offmsk, *tmp;
    float *bfu;
    unsigned *wfin, *wfout, *wff;
    cudaGetSymbolAddress((void**)&xproj,  g_xproj);
    cudaGetSymbolAddress((void**)&tmp,    g_tmp);
    cudaGetSymbolAddress((void**)&offmsk, g_offmsk);
    cudaGetSymbolAddress((void**)&bfu,    g_bfuse);
    cudaGetSymbolAddress((void**)&wfin,   g_wfrag_in);
    cudaGetSymbolAddress((void**)&wfout,  g_wfrag_out);
    cudaGetSymbolAddress((void**)&wff,    g_wffrag);

    cudaFuncSetAttribute(deform_gemm, cudaFuncAttributeMaxDynamicSharedMemorySize, SM_TOTAL);

    // 0. single prep kernel: pack w_in/w_out, fuse+pack W_f (N pad 192), bias
    prep_all<<<(27648 + NFUS + 255) / 256, 256>>>(
        w_in, w_out, w_pw, b_pw, w_off, b_off, w_mask, b_mask,
        wfin, wfout, wff, bfu);
    // 1. x_proj = x @ w_in + b_in  (fp16 mma, 32x48 warp tiles)
    gemm_f16<<<dim3(2, M_PIX / 128), 256>>>(x, wfin, b_in, xproj);
    // 2. depthwise 3x3 + SiLU -> fp16 tmp
    {
        size_t n = (size_t)(M_PIX / 4) * (Cc / 4);
        dw_silu<<<(unsigned)((n + 255) / 256), 256>>>(
            (const float4*)x, (const float4*)w_dw, (const float4*)b_dw, tmp);
    }
    // 3. [offsets|mask] = dwout_fp16 @ W_f + b_f -> fp16 offmsk (32x48 tiles)
    gemm_plain_direct<<<dim3(2, M_PIX / 128), 256>>>(tmp, wff, bfu, offmsk);
    // 4+5. fused softmax + deformable sampling (half2 lerp) + final GEMM -> out
    deform_gemm<<<2048, 256, SM_TOTAL>>>(xproj, offmsk, wfout, b_out, out);
}